// round 4
// baseline (speedup 1.0000x reference)
#include <cuda_runtime.h>
#include <math.h>

#define BATCH   8192
#define NSITES  256
#define DIM     128
#define NOUT    10
#define TS      64      // samples per CTA
#define NTHREADS 256
#define MIDSITES 254

// Scratch: feature map, site-major layout for coalesced per-site reads.
__device__ float g_phiC[NSITES * BATCH];
__device__ float g_phiS[NSITES * BATCH];

// ---------------------------------------------------------------------------
// f32x2 packed-math helpers (sm_10x; ptxas never auto-fuses these)
// ---------------------------------------------------------------------------
__device__ __forceinline__ unsigned long long dup_f32x2(float a) {
    unsigned long long r;
    asm("mov.b64 %0, {%1, %1};" : "=l"(r) : "f"(a));
    return r;
}
__device__ __forceinline__ void ffma2(unsigned long long& d,
                                      unsigned long long a,
                                      unsigned long long b) {
    asm("fma.rn.f32x2 %0, %1, %2, %0;" : "+l"(d) : "l"(a), "l"(b));
}
__device__ __forceinline__ float2 unpack2(unsigned long long v) {
    float2 f;
    asm("mov.b64 {%0, %1}, %2;" : "=f"(f.x), "=f"(f.y) : "l"(v));
    return f;
}
__device__ __forceinline__ void lds_v2b64(unsigned long long& a,
                                          unsigned long long& b,
                                          unsigned smem_addr) {
    asm volatile("ld.shared.v2.b64 {%0, %1}, [%2];"
                 : "=l"(a), "=l"(b) : "r"(smem_addr));
}

// ---------------------------------------------------------------------------
// Kernel 1: per-sample min/max normalization + (cos, sin) feature map.
// ---------------------------------------------------------------------------
__global__ void phi_kernel(const float* __restrict__ x) {
    const int b = blockIdx.x;
    const int n = threadIdx.x;
    const float v = x[b * NSITES + n];

    float mn = v, mx = v;
    #pragma unroll
    for (int off = 16; off > 0; off >>= 1) {
        mn = fminf(mn, __shfl_xor_sync(0xffffffffu, mn, off));
        mx = fmaxf(mx, __shfl_xor_sync(0xffffffffu, mx, off));
    }
    __shared__ float smn[8], smx[8];
    const int w = n >> 5, lane = n & 31;
    if (lane == 0) { smn[w] = mn; smx[w] = mx; }
    __syncthreads();
    mn = smn[0]; mx = smx[0];
    #pragma unroll
    for (int i = 1; i < 8; i++) {
        mn = fminf(mn, smn[i]);
        mx = fmaxf(mx, smx[i]);
    }
    const float ang = 1.57079632679489662f * (v - mn) / (mx - mn + 1e-6f);
    g_phiC[n * BATCH + b] = cosf(ang);
    g_phiS[n * BATCH + b] = sinf(ang);
}

// ---------------------------------------------------------------------------
// Kernel 2: MPS contraction, restructured as two matvecs + phi combine:
//   P0 = Lf @ W0,  P1 = Lf @ W1,  Lf' = c*P0 + s*P1
// Inner loop uses packed fma.rn.f32x2 (32 FFMA2/l/thread vs 80 fma ops before).
// ---------------------------------------------------------------------------
extern __shared__ float sm[];

__global__ __launch_bounds__(NTHREADS, 1)
void mps_kernel(const float* __restrict__ first,
                const float* __restrict__ mid,
                const float* __restrict__ last,
                const float* __restrict__ wlin,
                const float* __restrict__ blin,
                float* __restrict__ out) {
    float* W     = sm;                       // [256][128]  (row = 2l+d)
    float* Lf    = sm + 2 * DIM * DIM;       // [TS][128]
    float* sC    = Lf + TS * DIM;            // [TS]
    float* sS    = sC + TS;                  // [TS]
    float* sLast = sS + TS;                  // [256]

    const int b0  = blockIdx.x * TS;
    const int tid = threadIdx.x;
    const int tx  = tid & 31;                // output-column group
    const int ty  = tid >> 5;                // sample group (warp)
    const int r0  = tx * 4;
    const int sbase = ty * 8;

    const unsigned W_base  = (unsigned)__cvta_generic_to_shared(W) + r0 * 4u;
    const unsigned Lf_base = (unsigned)__cvta_generic_to_shared(Lf);

    // --- init left from site 0 ---
    for (int idx = tid; idx < TS * DIM; idx += NTHREADS) {
        const int s = idx >> 7, r = idx & 127;
        const float c0 = g_phiC[b0 + s];
        const float s0 = g_phiS[b0 + s];
        Lf[idx] = first[r] * c0 + first[DIM + r] * s0;
    }
    // --- preload W(0) and phi(site 1) ---
    {
        const float4* src = (const float4*)mid;
        float4* dst = (float4*)W;
        #pragma unroll 8
        for (int idx = tid; idx < 2 * DIM * DIM / 4; idx += NTHREADS)
            dst[idx] = src[idx];
        if (tid < TS)           sC[tid]      = g_phiC[1 * BATCH + b0 + tid];
        else if (tid < 2 * TS)  sS[tid - TS] = g_phiS[1 * BATCH + b0 + tid - TS];
    }
    __syncthreads();

    for (int site = 0; site < MIDSITES; ++site) {
        float c[8], s[8];
        #pragma unroll
        for (int j = 0; j < 8; j++) { c[j] = sC[sbase + j]; s[j] = sS[sbase + j]; }

        // acc0 = P0 (pairs over r), acc1 = P1
        unsigned long long acc0[8][2], acc1[8][2];
        #pragma unroll
        for (int j = 0; j < 8; j++) {
            acc0[j][0] = 0ull; acc0[j][1] = 0ull;
            acc1[j][0] = 0ull; acc1[j][1] = 0ull;
        }

        #pragma unroll 1
        for (int lb = 0; lb < DIM; lb += 4) {
            // broadcast-load 4 l's of 'a' per sample
            float4 a4[8];
            #pragma unroll
            for (int j = 0; j < 8; j++)
                a4[j] = *(const float4*)(Lf + (sbase + j) * DIM + lb);

            #pragma unroll
            for (int li = 0; li < 4; ++li) {
                const int l = lb + li;
                unsigned long long w0a, w0b, w1a, w1b;
                lds_v2b64(w0a, w0b, W_base + (2 * l)     * (DIM * 4u));
                lds_v2b64(w1a, w1b, W_base + (2 * l + 1) * (DIM * 4u));
                #pragma unroll
                for (int j = 0; j < 8; j++) {
                    const float a = (li == 0) ? a4[j].x : (li == 1) ? a4[j].y
                                  : (li == 2) ? a4[j].z : a4[j].w;
                    const unsigned long long aa = dup_f32x2(a);
                    ffma2(acc0[j][0], aa, w0a);
                    ffma2(acc0[j][1], aa, w0b);
                    ffma2(acc1[j][0], aa, w1a);
                    ffma2(acc1[j][1], aa, w1b);
                }
            }
        }
        __syncthreads();   // all reads of Lf / W / sC / sS for this site done

        // epilogue: Lf' = c*P0 + s*P1
        #pragma unroll
        for (int j = 0; j < 8; j++) {
            const float2 p0a = unpack2(acc0[j][0]), p0b = unpack2(acc0[j][1]);
            const float2 p1a = unpack2(acc1[j][0]), p1b = unpack2(acc1[j][1]);
            float4 v;
            v.x = fmaf(c[j], p0a.x, s[j] * p1a.x);
            v.y = fmaf(c[j], p0a.y, s[j] * p1a.y);
            v.z = fmaf(c[j], p0b.x, s[j] * p1b.x);
            v.w = fmaf(c[j], p0b.y, s[j] * p1b.y);
            *(float4*)&Lf[(sbase + j) * DIM + r0] = v;
        }

        // stage next site's W + phi (or the final-site data)
        if (site < MIDSITES - 1) {
            const float4* src = (const float4*)(mid + (size_t)(site + 1) * (2 * DIM * DIM));
            float4* dst = (float4*)W;
            #pragma unroll 8
            for (int idx = tid; idx < 2 * DIM * DIM / 4; idx += NTHREADS)
                dst[idx] = src[idx];
            const int ph = site + 2;
            if (tid < TS)           sC[tid]      = g_phiC[ph * BATCH + b0 + tid];
            else if (tid < 2 * TS)  sS[tid - TS] = g_phiS[ph * BATCH + b0 + tid - TS];
        } else {
            sLast[tid] = last[tid];
            if (tid < TS)           sC[tid]      = g_phiC[(NSITES - 1) * BATCH + b0 + tid];
            else if (tid < 2 * TS)  sS[tid - TS] = g_phiS[(NSITES - 1) * BATCH + b0 + tid - TS];
        }
        __syncthreads();
    }

    // --- final contraction + linear head ---
    if (tid < TS) {
        const float cL = sC[tid], sL = sS[tid];
        float acc = 0.0f;
        #pragma unroll 4
        for (int l = 0; l < DIM; ++l)
            acc = fmaf(Lf[tid * DIM + l],
                       fmaf(sLast[2 * l], cL, sLast[2 * l + 1] * sL), acc);
        #pragma unroll
        for (int o = 0; o < NOUT; o++)
            out[(b0 + tid) * NOUT + o] = fmaf(acc, wlin[o], blin[o]);
    }
}

// ---------------------------------------------------------------------------
extern "C" void kernel_launch(void* const* d_in, const int* in_sizes, int n_in,
                              void* d_out, int out_size) {
    const float* x     = (const float*)d_in[0];
    const float* first = (const float*)d_in[1];
    const float* mid   = (const float*)d_in[2];
    const float* last  = (const float*)d_in[3];
    const float* wlin  = (const float*)d_in[4];
    const float* blin  = (const float*)d_in[5];
    float* out = (float*)d_out;

    const int smem_bytes = (2 * DIM * DIM + TS * DIM + 2 * TS + 256) * sizeof(float);
    cudaFuncSetAttribute(mps_kernel, cudaFuncAttributeMaxDynamicSharedMemorySize,
                         smem_bytes);

    phi_kernel<<<BATCH, NSITES>>>(x);
    mps_kernel<<<BATCH / TS, NTHREADS, smem_bytes>>>(first, mid, last, wlin, blin, out);
}

// round 6
// speedup vs baseline: 2.6249x; 2.6249x over previous
#include <cuda_runtime.h>
#include <cuda_bf16.h>
#include <cstdint>
#include <math.h>

#define BATCH    8192
#define NSITES   256
#define DIM      128
#define NOUT     10
#define TSS      64
#define NTHREADS 256
#define MIDSITES 254
#define K2       256
#define VSTRIDE  132

// smem byte offsets
#define OFF_AHI  0        // 65536 B : A_hi [128][256] bf16, swizzled
#define OFF_ALO  65536    // 65536 B
#define OFF_BHI  131072   // 32768 B : B_hi [64][256] bf16, swizzled
#define OFF_BLO  163840   // 32768 B
#define OFF_V    196608   // 33792 B : V [64][132] fp32
#define SMEM_TOTAL 230400

__device__ float    g_phiC[NSITES * BATCH];
__device__ float    g_phiS[NSITES * BATCH];
__device__ uint16_t g_Ahi[(size_t)MIDSITES * DIM * K2];
__device__ uint16_t g_Alo[(size_t)MIDSITES * DIM * K2];

// ---------------------------------------------------------------------------
// helpers
// ---------------------------------------------------------------------------
__device__ __forceinline__ uint32_t swz(int row, int k) {
    // 512B rows, 16B chunks, chunk ^= row&7 (period-8 XOR swizzle)
    const int chunk = k >> 3;
    return (uint32_t)(row * 512 + (((chunk & 24) | ((chunk ^ row) & 7)) << 4)
                      + ((k & 7) << 1));
}

__device__ __forceinline__ void split4(float4 f, uint32_t& h01, uint32_t& h23,
                                       uint32_t& l01, uint32_t& l23) {
    asm("cvt.rn.bf16x2.f32 %0, %1, %2;" : "=r"(h01) : "f"(f.y), "f"(f.x));
    asm("cvt.rn.bf16x2.f32 %0, %1, %2;" : "=r"(h23) : "f"(f.w), "f"(f.z));
    const float hx = __uint_as_float(h01 << 16);
    const float hy = __uint_as_float(h01 & 0xffff0000u);
    const float hz = __uint_as_float(h23 << 16);
    const float hw = __uint_as_float(h23 & 0xffff0000u);
    const float lx = f.x - hx, ly = f.y - hy, lz = f.z - hz, lw = f.w - hw;
    asm("cvt.rn.bf16x2.f32 %0, %1, %2;" : "=r"(l01) : "f"(ly), "f"(lx));
    asm("cvt.rn.bf16x2.f32 %0, %1, %2;" : "=r"(l23) : "f"(lw), "f"(lz));
}

__device__ __forceinline__ void ldsm4(uint32_t r[4], uint32_t addr) {
    asm volatile("ldmatrix.sync.aligned.m8n8.x4.shared.b16 {%0,%1,%2,%3}, [%4];"
                 : "=r"(r[0]), "=r"(r[1]), "=r"(r[2]), "=r"(r[3]) : "r"(addr));
}

__device__ __forceinline__ void mma_bf16(float c[4], const uint32_t a[4],
                                         const uint32_t b[2]) {
    asm volatile("mma.sync.aligned.m16n8k16.row.col.f32.bf16.bf16.f32 "
                 "{%0,%1,%2,%3}, {%4,%5,%6,%7}, {%8,%9}, {%0,%1,%2,%3};"
                 : "+f"(c[0]), "+f"(c[1]), "+f"(c[2]), "+f"(c[3])
                 : "r"(a[0]), "r"(a[1]), "r"(a[2]), "r"(a[3]),
                   "r"(b[0]), "r"(b[1]));
}

#define CP_ASYNC16(dst, src) \
    asm volatile("cp.async.cg.shared.global [%0], [%1], 16;" \
                 :: "r"(dst), "l"(src) : "memory")
#define CP_COMMIT() asm volatile("cp.async.commit_group;" ::: "memory")
#define CP_WAIT0()  asm volatile("cp.async.wait_group 0;" ::: "memory")

// ---------------------------------------------------------------------------
// Kernel 0: split mid into bf16 hi/lo, pre-swizzled smem image layout
// ---------------------------------------------------------------------------
__global__ void split_mid(const float* __restrict__ mid) {
    const int gid = blockIdx.x * blockDim.x + threadIdx.x;   // quad index
    if (gid >= MIDSITES * (DIM * K2 / 4)) return;
    const int site = gid >> 13;          // / 8192
    const int q    = gid & 8191;
    const int l    = q >> 6;
    const int k    = (q & 63) << 2;
    const float4 w = *(const float4*)(mid + (size_t)site * (DIM * K2) + l * K2 + k);
    uint32_t h01, h23, l01, l23;
    split4(w, h01, h23, l01, l23);
    const size_t base = (size_t)site * (DIM * K2) * 2;   // bytes
    const uint32_t bo = swz(l, k);
    *(uint2*)((char*)g_Ahi + base + bo) = make_uint2(h01, h23);
    *(uint2*)((char*)g_Alo + base + bo) = make_uint2(l01, l23);
}

// ---------------------------------------------------------------------------
// Kernel 1: feature map
// ---------------------------------------------------------------------------
__global__ void phi_kernel(const float* __restrict__ x) {
    const int b = blockIdx.x;
    const int n = threadIdx.x;
    const float v = x[b * NSITES + n];
    float mn = v, mx = v;
    #pragma unroll
    for (int off = 16; off > 0; off >>= 1) {
        mn = fminf(mn, __shfl_xor_sync(0xffffffffu, mn, off));
        mx = fmaxf(mx, __shfl_xor_sync(0xffffffffu, mx, off));
    }
    __shared__ float smn[8], smx[8];
    const int w = n >> 5, lane = n & 31;
    if (lane == 0) { smn[w] = mn; smx[w] = mx; }
    __syncthreads();
    mn = smn[0]; mx = smx[0];
    #pragma unroll
    for (int i = 1; i < 8; i++) { mn = fminf(mn, smn[i]); mx = fmaxf(mx, smx[i]); }
    const float ang = 1.57079632679489662f * (v - mn) / (mx - mn + 1e-6f);
    g_phiC[n * BATCH + b] = cosf(ang);
    g_phiS[n * BATCH + b] = sinf(ang);
}

// ---------------------------------------------------------------------------
// Kernel 2: reversed-chain MPS on mma.sync bf16 (3-term compensated)
//   D[l][s] = sum_k A[l][k] * B[s][k];  A = mid[site] (hi/lo), B = phi (x) v
// ---------------------------------------------------------------------------
extern __shared__ char smem_raw[];

__global__ __launch_bounds__(NTHREADS, 1)
void mps_mma(const float* __restrict__ first,
             const float* __restrict__ last,
             const float* __restrict__ wlin,
             const float* __restrict__ blin,
             float* __restrict__ out) {
    const uint32_t sbase = (uint32_t)__cvta_generic_to_shared(smem_raw);
    float* V   = (float*)(smem_raw + OFF_V);
    char* sBh  = smem_raw + OFF_BHI;
    char* sBl  = smem_raw + OFF_BLO;
    const int tid  = threadIdx.x;
    const int wid  = tid >> 5, lane = tid & 31;
    const int b0   = blockIdx.x * TSS;
    const int wm   = wid & 3,  wn = wid >> 2;
    const int m_base = wm * 32, s_base = wn * 32;

    // ldmatrix per-lane bases
    const int rowA = m_base + (lane & 15);
    const int cA   = lane >> 4;                               // A k-half bit
    const int r7a  = rowA & 7;
    const uint32_t baseAhi = sbase + OFF_AHI + rowA * 512;
    const uint32_t baseAlo = sbase + OFF_ALO + rowA * 512;
    const int rowB = s_base + ((lane >> 4) << 3) + (lane & 7);
    const int cB   = (lane >> 3) & 1;                         // B k-half bit
    const int r7b  = rowB & 7;
    const uint32_t baseBhi = sbase + OFF_BHI + rowB * 512;
    const uint32_t baseBlo = sbase + OFF_BLO + rowB * 512;

    // ---- initial B (A = mid[253], phi site 254, v from last & phi 255) ----
    {
        const int s = tid & 63, p = tid >> 6;
        const float cL = g_phiC[(size_t)(NSITES - 1) * BATCH + b0 + s];
        const float sL = g_phiS[(size_t)(NSITES - 1) * BATCH + b0 + s];
        const float cp = g_phiC[(size_t)(NSITES - 2) * BATCH + b0 + s];
        const float sp = g_phiS[(size_t)(NSITES - 2) * BATCH + b0 + s];
        for (int r = p * 32; r < p * 32 + 32; r += 4) {
            float4 v;
            v.x = last[2*r+0]*cL + last[2*r+1]*sL;
            v.y = last[2*r+2]*cL + last[2*r+3]*sL;
            v.z = last[2*r+4]*cL + last[2*r+5]*sL;
            v.w = last[2*r+6]*cL + last[2*r+7]*sL;
            float4 f0 = make_float4(cp*v.x, cp*v.y, cp*v.z, cp*v.w);
            float4 f1 = make_float4(sp*v.x, sp*v.y, sp*v.z, sp*v.w);
            uint32_t h01,h23,l01,l23;
            uint32_t o = swz(s, r);
            split4(f0, h01,h23,l01,l23);
            *(uint2*)(sBh + o) = make_uint2(h01,h23);
            *(uint2*)(sBl + o) = make_uint2(l01,l23);
            o = swz(s, DIM + r);
            split4(f1, h01,h23,l01,l23);
            *(uint2*)(sBh + o) = make_uint2(h01,h23);
            *(uint2*)(sBl + o) = make_uint2(l01,l23);
        }
    }
    // ---- initial A stage ----
    {
        const char* srcH = (const char*)g_Ahi + (size_t)(MIDSITES - 1) * 65536;
        const char* srcL = (const char*)g_Alo + (size_t)(MIDSITES - 1) * 65536;
        for (int j = tid * 16; j < 65536; j += NTHREADS * 16) {
            CP_ASYNC16(sbase + OFF_AHI + j, srcH + j);
            CP_ASYNC16(sbase + OFF_ALO + j, srcL + j);
        }
        CP_COMMIT(); CP_WAIT0();
    }
    __syncthreads();

    for (int it = 0; it < MIDSITES; ++it) {
        const int mid_idx = MIDSITES - 1 - it;
        const bool last_it = (it == MIDSITES - 1);

        float acc[2][4][4];
        #pragma unroll
        for (int mi = 0; mi < 2; mi++)
            #pragma unroll
            for (int ni = 0; ni < 4; ni++)
                #pragma unroll
                for (int e = 0; e < 4; e++) acc[mi][ni][e] = 0.0f;

        #pragma unroll
        for (int st = 0; st < 16; ++st) {
            const int chA = 2 * st + cA;
            const uint32_t tA = (uint32_t)(((chA & 24) | ((chA & 7) ^ r7a)) << 4);
            const int chB = 2 * st + cB;
            const uint32_t tB = (uint32_t)(((chB & 24) | ((chB & 7) ^ r7b)) << 4);
            uint32_t ah0[4], ah1[4], al0[4], al1[4], q[4];
            ldsm4(ah0, baseAhi + tA);
            ldsm4(ah1, baseAhi + tA + 8192);
            ldsm4(al0, baseAlo + tA);
            ldsm4(al1, baseAlo + tA + 8192);
            uint32_t bh[4][2], bl[4][2];
            ldsm4(q, baseBhi + tB);
            bh[0][0]=q[0]; bh[0][1]=q[1]; bh[1][0]=q[2]; bh[1][1]=q[3];
            ldsm4(q, baseBhi + tB + 8192);
            bh[2][0]=q[0]; bh[2][1]=q[1]; bh[3][0]=q[2]; bh[3][1]=q[3];
            ldsm4(q, baseBlo + tB);
            bl[0][0]=q[0]; bl[0][1]=q[1]; bl[1][0]=q[2]; bl[1][1]=q[3];
            ldsm4(q, baseBlo + tB + 8192);
            bl[2][0]=q[0]; bl[2][1]=q[1]; bl[3][0]=q[2]; bl[3][1]=q[3];
            #pragma unroll
            for (int ni = 0; ni < 4; ni++) {
                mma_bf16(acc[0][ni], ah0, bh[ni]);
                mma_bf16(acc[1][ni], ah1, bh[ni]);
                mma_bf16(acc[0][ni], al0, bh[ni]);
                mma_bf16(acc[1][ni], al1, bh[ni]);
                mma_bf16(acc[0][ni], ah0, bl[ni]);
                mma_bf16(acc[1][ni], ah1, bl[ni]);
            }
        }
        __syncthreads();   // all warps done reading A/B smem

        // overlap: kick next-site A copy while we do the epilogue
        if (!last_it) {
            const char* srcH = (const char*)g_Ahi + (size_t)(mid_idx - 1) * 65536;
            const char* srcL = (const char*)g_Alo + (size_t)(mid_idx - 1) * 65536;
            #pragma unroll 4
            for (int j = tid * 16; j < 65536; j += NTHREADS * 16) {
                CP_ASYNC16(sbase + OFF_AHI + j, srcH + j);
                CP_ASYNC16(sbase + OFF_ALO + j, srcL + j);
            }
            CP_COMMIT();
        }

        // store C fragments -> V[s][l] (transposed)
        const int rr = lane >> 2, cq = (lane & 3) * 2;
        #pragma unroll
        for (int mi = 0; mi < 2; mi++)
            #pragma unroll
            for (int ni = 0; ni < 4; ni++) {
                const int l = m_base + 16 * mi + rr;
                const int s = s_base + 8 * ni + cq;
                V[s * VSTRIDE + l]           = acc[mi][ni][0];
                V[(s + 1) * VSTRIDE + l]     = acc[mi][ni][1];
                V[s * VSTRIDE + l + 8]       = acc[mi][ni][2];
                V[(s + 1) * VSTRIDE + l + 8] = acc[mi][ni][3];
            }
        __syncthreads();   // V complete

        if (!last_it) {
            // build next B: B[s][k=r] = c*v[s][r], B[s][128+r] = s*v[s][r]
            const int s = tid & 63, p = tid >> 6;
            const float cp_ = g_phiC[(size_t)mid_idx * BATCH + b0 + s];
            const float sp_ = g_phiS[(size_t)mid_idx * BATCH + b0 + s];
            #pragma unroll 4
            for (int r = p * 32; r < p * 32 + 32; r += 4) {
                const float4 v = *(const float4*)&V[s * VSTRIDE + r];
                float4 f0 = make_float4(cp_*v.x, cp_*v.y, cp_*v.z, cp_*v.w);
                float4 f1 = make_float4(sp_*v.x, sp_*v.y, sp_*v.z, sp_*v.w);
                uint32_t h01,h23,l01,l23;
                uint32_t o = swz(s, r);
                split4(f0, h01,h23,l01,l23);
                *(uint2*)(sBh + o) = make_uint2(h01,h23);
                *(uint2*)(sBl + o) = make_uint2(l01,l23);
                o = swz(s, DIM + r);
                split4(f1, h01,h23,l01,l23);
                *(uint2*)(sBh + o) = make_uint2(h01,h23);
                *(uint2*)(sBl + o) = make_uint2(l01,l23);
            }
        } else if (tid < TSS) {
            // final head: scalar = sum_l (first[l]c0 + first[128+l]s0) * V[s][l]
            const int s = tid;
            const float c0 = g_phiC[b0 + s];
            const float s0 = g_phiS[b0 + s];
            float accs = 0.0f;
            #pragma unroll 4
            for (int l = 0; l < DIM; l++) {
                const float lv = fmaf(first[l], c0, first[DIM + l] * s0);
                accs = fmaf(lv, V[s * VSTRIDE + l], accs);
            }
            #pragma unroll
            for (int o = 0; o < NOUT; o++)
                out[(b0 + s) * NOUT + o] = fmaf(accs, wlin[o], blin[o]);
        }
        CP_WAIT0();        // next A landed (no-op on last iteration)
        __syncthreads();
    }
}

// ---------------------------------------------------------------------------
extern "C" void kernel_launch(void* const* d_in, const int* in_sizes, int n_in,
                              void* d_out, int out_size) {
    const float* x     = (const float*)d_in[0];
    const float* first = (const float*)d_in[1];
    const float* mid   = (const float*)d_in[2];
    const float* last  = (const float*)d_in[3];
    const float* wlin  = (const float*)d_in[4];
    const float* blin  = (const float*)d_in[5];
    float* out = (float*)d_out;

    cudaFuncSetAttribute(mps_mma, cudaFuncAttributeMaxDynamicSharedMemorySize,
                         SMEM_TOTAL);

    split_mid<<<(MIDSITES * DIM * K2 / 4 + 255) / 256, 256>>>(mid);
    phi_kernel<<<BATCH, NSITES>>>(x);
    mps_mma<<<BATCH / TSS, NTHREADS, SMEM_TOTAL>>>(first, last, wlin, blin, out);
}

// round 7
// speedup vs baseline: 2.8183x; 1.0737x over previous
#include <cuda_runtime.h>
#include <cuda_bf16.h>
#include <cstdint>
#include <math.h>

#define BATCH    8192
#define NSITES   256
#define DIM      128
#define NOUT     10
#define TSS      64
#define NTHREADS 256
#define MIDSITES 254
#define K2       256
#define VSTRIDE  132

// smem byte offsets
#define OFF_A0HI 0        // 32 KB : A_hi K-half 0, [128 rows][256B] swizzled
#define OFF_A0LO 32768
#define OFF_A1HI 65536
#define OFF_A1LO 98304
#define OFF_BHI  131072   // 32 KB : B_hi [64 rows][512B] swizzled
#define OFF_BLO  163840
#define OFF_V    196608   // 33792 B : V [64][132] fp32
#define OFF_MB0  230400   // mbarrier buf0
#define OFF_MB1  230408   // mbarrier buf1
#define SMEM_TOTAL 230416

__device__ float    g_phiC[NSITES * BATCH];
__device__ float    g_phiS[NSITES * BATCH];
// per site: [khalf][128 rows][256B] contiguous per half (32 KB), hi/lo separate
__device__ uint16_t g_Ahi[(size_t)MIDSITES * DIM * K2];
__device__ uint16_t g_Alo[(size_t)MIDSITES * DIM * K2];

// ---------------------------------------------------------------------------
// helpers
// ---------------------------------------------------------------------------
__device__ __forceinline__ void split4(float4 f, uint32_t& h01, uint32_t& h23,
                                       uint32_t& l01, uint32_t& l23) {
    asm("cvt.rn.bf16x2.f32 %0, %1, %2;" : "=r"(h01) : "f"(f.y), "f"(f.x));
    asm("cvt.rn.bf16x2.f32 %0, %1, %2;" : "=r"(h23) : "f"(f.w), "f"(f.z));
    const float hx = __uint_as_float(h01 << 16);
    const float hy = __uint_as_float(h01 & 0xffff0000u);
    const float hz = __uint_as_float(h23 << 16);
    const float hw = __uint_as_float(h23 & 0xffff0000u);
    const float lx = f.x - hx, ly = f.y - hy, lz = f.z - hz, lw = f.w - hw;
    asm("cvt.rn.bf16x2.f32 %0, %1, %2;" : "=r"(l01) : "f"(ly), "f"(lx));
    asm("cvt.rn.bf16x2.f32 %0, %1, %2;" : "=r"(l23) : "f"(lw), "f"(lz));
}

__device__ __forceinline__ void ldsm4(uint32_t r[4], uint32_t addr) {
    asm volatile("ldmatrix.sync.aligned.m8n8.x4.shared.b16 {%0,%1,%2,%3}, [%4];"
                 : "=r"(r[0]), "=r"(r[1]), "=r"(r[2]), "=r"(r[3]) : "r"(addr));
}

__device__ __forceinline__ void mma_bf16(float c[4], const uint32_t a[4],
                                         const uint32_t b[2]) {
    asm volatile("mma.sync.aligned.m16n8k16.row.col.f32.bf16.bf16.f32 "
                 "{%0,%1,%2,%3}, {%4,%5,%6,%7}, {%8,%9}, {%0,%1,%2,%3};"
                 : "+f"(c[0]), "+f"(c[1]), "+f"(c[2]), "+f"(c[3])
                 : "r"(a[0]), "r"(a[1]), "r"(a[2]), "r"(a[3]),
                   "r"(b[0]), "r"(b[1]));
}

#define MBARRIER_INIT(a, c) \
    asm volatile("mbarrier.init.shared.b64 [%0], %1;" \
                 :: "r"((uint32_t)(a)), "r"((uint32_t)(c)) : "memory")
#define MBARRIER_EXPECT_TX(a, n) \
    asm volatile("mbarrier.arrive.expect_tx.shared.b64 _, [%0], %1;" \
                 :: "r"((uint32_t)(a)), "r"((uint32_t)(n)) : "memory")
#define BULK_CP(dst, src, n, mbar) \
    asm volatile("cp.async.bulk.shared::cluster.global.mbarrier::complete_tx::bytes " \
                 "[%0], [%1], %2, [%3];" \
                 :: "r"((uint32_t)(dst)), "l"(src), "r"((uint32_t)(n)), \
                    "r"((uint32_t)(mbar)) : "memory")
#define MBAR_WAIT(mbar, ph) do {                                             \
    uint32_t _m = (uint32_t)(mbar); uint32_t _p = (uint32_t)(ph);            \
    asm volatile("{\n\t.reg .pred P1;\n\t"                                   \
        "WAIT_%=:\n\t"                                                        \
        "mbarrier.try_wait.parity.acquire.cta.shared::cta.b64 P1, [%0], %1, 0x989680;\n\t" \
        "@P1 bra.uni DONE_%=;\n\t"                                            \
        "bra.uni WAIT_%=;\n\t"                                                \
        "DONE_%=:\n\t}" :: "r"(_m), "r"(_p) : "memory");                      \
} while (0)

// ---------------------------------------------------------------------------
// Kernel 0: split mid into bf16 hi/lo, K-half-contiguous swizzled layout
// ---------------------------------------------------------------------------
__global__ void split_mid(const float* __restrict__ mid) {
    const int gid = blockIdx.x * blockDim.x + threadIdx.x;   // quad index
    if (gid >= MIDSITES * (DIM * K2 / 4)) return;
    const int site = gid >> 13;
    const int q    = gid & 8191;
    const int l    = q >> 6;
    const int k    = (q & 63) << 2;
    const float4 w = *(const float4*)(mid + (size_t)site * (DIM * K2) + l * K2 + k);
    uint32_t h01, h23, l01, l23;
    split4(w, h01, h23, l01, l23);
    const int khalf = k >> 7;
    const int chunk = (k >> 3) & 15;
    const size_t bo = (size_t)site * 65536 + (size_t)khalf * 32768
                    + (size_t)l * 256
                    + (uint32_t)(((chunk & 8) | ((chunk ^ (l & 7)) & 7)) << 4)
                    + (uint32_t)((k & 7) << 1);
    *(uint2*)((char*)g_Ahi + bo) = make_uint2(h01, h23);
    *(uint2*)((char*)g_Alo + bo) = make_uint2(l01, l23);
}

// ---------------------------------------------------------------------------
// Kernel 1: feature map
// ---------------------------------------------------------------------------
__global__ void phi_kernel(const float* __restrict__ x) {
    const int b = blockIdx.x;
    const int n = threadIdx.x;
    const float v = x[b * NSITES + n];
    float mn = v, mx = v;
    #pragma unroll
    for (int off = 16; off > 0; off >>= 1) {
        mn = fminf(mn, __shfl_xor_sync(0xffffffffu, mn, off));
        mx = fmaxf(mx, __shfl_xor_sync(0xffffffffu, mx, off));
    }
    __shared__ float smn[8], smx[8];
    const int w = n >> 5, lane = n & 31;
    if (lane == 0) { smn[w] = mn; smx[w] = mx; }
    __syncthreads();
    mn = smn[0]; mx = smx[0];
    #pragma unroll
    for (int i = 1; i < 8; i++) { mn = fminf(mn, smn[i]); mx = fmaxf(mx, smx[i]); }
    const float ang = 1.57079632679489662f * (v - mn) / (mx - mn + 1e-6f);
    g_phiC[n * BATCH + b] = cosf(ang);
    g_phiS[n * BATCH + b] = sinf(ang);
}

// ---------------------------------------------------------------------------
// Kernel 2: reversed-chain MPS, mma.sync bf16 3-term, K-half pipelined TMA
// ---------------------------------------------------------------------------
extern __shared__ char smem_raw[];

__global__ __launch_bounds__(NTHREADS, 1)
void mps_mma(const float* __restrict__ first,
             const float* __restrict__ last,
             const float* __restrict__ wlin,
             const float* __restrict__ blin,
             float* __restrict__ out) {
    const uint32_t sbase = (uint32_t)__cvta_generic_to_shared(smem_raw);
    float* V   = (float*)(smem_raw + OFF_V);
    char* sBh  = smem_raw + OFF_BHI;
    char* sBl  = smem_raw + OFF_BLO;
    const uint32_t mb0 = sbase + OFF_MB0, mb1 = sbase + OFF_MB1;
    const int tid  = threadIdx.x;
    const int wid  = tid >> 5, lane = tid & 31;
    const int b0   = blockIdx.x * TSS;
    const int wm   = wid & 3,  wn = wid >> 2;
    const int m_base = wm * 32, s_base = wn * 32;

    // ldmatrix per-lane bases
    const int rowA = m_base + (lane & 15);
    const int cA   = lane >> 4;
    const int r7a  = rowA & 7;
    const uint32_t a0hi = sbase + OFF_A0HI + rowA * 256;
    const uint32_t a0lo = sbase + OFF_A0LO + rowA * 256;
    const uint32_t a1hi = sbase + OFF_A1HI + rowA * 256;
    const uint32_t a1lo = sbase + OFF_A1LO + rowA * 256;
    const int rowB = s_base + ((lane >> 4) << 3) + (lane & 7);
    const int cB   = (lane >> 3) & 1;
    const int r7b  = rowB & 7;
    const uint32_t baseBhi = sbase + OFF_BHI + rowB * 512;
    const uint32_t baseBlo = sbase + OFF_BLO + rowB * 512;

    if (tid == 0) { MBARRIER_INIT(mb0, 1); MBARRIER_INIT(mb1, 1); }
    __syncthreads();

    // ---- prologue: TMA both K-halves of site 253 ----
    if (tid == 0) {
        const char* hi = (const char*)g_Ahi + (size_t)(MIDSITES - 1) * 65536;
        const char* lo = (const char*)g_Alo + (size_t)(MIDSITES - 1) * 65536;
        MBARRIER_EXPECT_TX(mb0, 65536);
        BULK_CP(sbase + OFF_A0HI, hi,         32768, mb0);
        BULK_CP(sbase + OFF_A0LO, lo,         32768, mb0);
        MBARRIER_EXPECT_TX(mb1, 65536);
        BULK_CP(sbase + OFF_A1HI, hi + 32768, 32768, mb1);
        BULK_CP(sbase + OFF_A1LO, lo + 32768, 32768, mb1);
    }

    // ---- initial B (v from last & phi[255], scaled by phi[254]) ----
    {
        const int s = tid & 63, p = tid >> 6;
        const float cL = g_phiC[(size_t)(NSITES - 1) * BATCH + b0 + s];
        const float sL = g_phiS[(size_t)(NSITES - 1) * BATCH + b0 + s];
        const float cp = g_phiC[(size_t)(NSITES - 2) * BATCH + b0 + s];
        const float sp = g_phiS[(size_t)(NSITES - 2) * BATCH + b0 + s];
        for (int r = p * 32; r < p * 32 + 32; r += 4) {
            float4 v;
            v.x = last[2*r+0]*cL + last[2*r+1]*sL;
            v.y = last[2*r+2]*cL + last[2*r+3]*sL;
            v.z = last[2*r+4]*cL + last[2*r+5]*sL;
            v.w = last[2*r+6]*cL + last[2*r+7]*sL;
            float4 f0 = make_float4(cp*v.x, cp*v.y, cp*v.z, cp*v.w);
            float4 f1 = make_float4(sp*v.x, sp*v.y, sp*v.z, sp*v.w);
            uint32_t h01,h23,l01,l23;
            const int ch0 = r >> 3;
            uint32_t o = (uint32_t)(s * 512 + (((ch0 & 24) | ((ch0 ^ (s & 7)) & 7)) << 4)
                                    + ((r & 7) << 1));
            split4(f0, h01,h23,l01,l23);
            *(uint2*)(sBh + o) = make_uint2(h01,h23);
            *(uint2*)(sBl + o) = make_uint2(l01,l23);
            const int ch1 = (DIM + r) >> 3;
            o = (uint32_t)(s * 512 + (((ch1 & 24) | ((ch1 ^ (s & 7)) & 7)) << 4)
                           + ((r & 7) << 1));
            split4(f1, h01,h23,l01,l23);
            *(uint2*)(sBh + o) = make_uint2(h01,h23);
            *(uint2*)(sBl + o) = make_uint2(l01,l23);
        }
    }
    __syncthreads();

    for (int it = 0; it < MIDSITES; ++it) {
        const int mid_idx = MIDSITES - 1 - it;
        const bool last_it = (it == MIDSITES - 1);
        const int ph = it & 1;

        float acc[2][4][4];
        #pragma unroll
        for (int mi = 0; mi < 2; mi++)
            #pragma unroll
            for (int ni = 0; ni < 4; ni++)
                #pragma unroll
                for (int e = 0; e < 4; e++) acc[mi][ni][e] = 0.0f;

        // ===== K-half 0 =====
        MBAR_WAIT(mb0, ph);
        #pragma unroll
        for (int st = 0; st < 8; ++st) {
            const int chA = 2 * st + cA;
            const uint32_t tA = (uint32_t)(((chA & 8) | ((chA ^ r7a) & 7)) << 4);
            const int chB = 2 * st + cB;
            const uint32_t tB = (uint32_t)(((chB & 24) | ((chB ^ r7b) & 7)) << 4);
            uint32_t ah0[4], ah1[4], al0[4], al1[4], q[4];
            ldsm4(ah0, a0hi + tA);
            ldsm4(ah1, a0hi + tA + 4096);
            ldsm4(al0, a0lo + tA);
            ldsm4(al1, a0lo + tA + 4096);
            uint32_t bh[4][2], bl[4][2];
            ldsm4(q, baseBhi + tB);
            bh[0][0]=q[0]; bh[0][1]=q[1]; bh[1][0]=q[2]; bh[1][1]=q[3];
            ldsm4(q, baseBhi + tB + 8192);
            bh[2][0]=q[0]; bh[2][1]=q[1]; bh[3][0]=q[2]; bh[3][1]=q[3];
            ldsm4(q, baseBlo + tB);
            bl[0][0]=q[0]; bl[0][1]=q[1]; bl[1][0]=q[2]; bl[1][1]=q[3];
            ldsm4(q, baseBlo + tB + 8192);
            bl[2][0]=q[0]; bl[2][1]=q[1]; bl[3][0]=q[2]; bl[3][1]=q[3];
            #pragma unroll
            for (int ni = 0; ni < 4; ni++) {
                mma_bf16(acc[0][ni], ah0, bh[ni]);
                mma_bf16(acc[1][ni], ah1, bh[ni]);
                mma_bf16(acc[0][ni], al0, bh[ni]);
                mma_bf16(acc[1][ni], al1, bh[ni]);
                mma_bf16(acc[0][ni], ah0, bl[ni]);
                mma_bf16(acc[1][ni], ah1, bl[ni]);
            }
        }
        __syncthreads();          // buf0 reads done
        if (!last_it && tid == 0) {
            const char* hi = (const char*)g_Ahi + (size_t)(mid_idx - 1) * 65536;
            const char* lo = (const char*)g_Alo + (size_t)(mid_idx - 1) * 65536;
            MBARRIER_EXPECT_TX(mb0, 65536);
            BULK_CP(sbase + OFF_A0HI, hi, 32768, mb0);
            BULK_CP(sbase + OFF_A0LO, lo, 32768, mb0);
        }

        // ===== K-half 1 =====
        MBAR_WAIT(mb1, ph);
        #pragma unroll
        for (int st = 0; st < 8; ++st) {
            const int chA = 2 * st + cA;
            const uint32_t tA = (uint32_t)(((chA & 8) | ((chA ^ r7a) & 7)) << 4);
            const int chB = 16 + 2 * st + cB;
            const uint32_t tB = (uint32_t)(((chB & 24) | ((chB ^ r7b) & 7)) << 4);
            uint32_t ah0[4], ah1[4], al0[4], al1[4], q[4];
            ldsm4(ah0, a1hi + tA);
            ldsm4(ah1, a1hi + tA + 4096);
            ldsm4(al0, a1lo + tA);
            ldsm4(al1, a1lo + tA + 4096);
            uint32_t bh[4][2], bl[4][2];
            ldsm4(q, baseBhi + tB);
            bh[0][0]=q[0]; bh[0][1]=q[1]; bh[1][0]=q[2]; bh[1][1]=q[3];
            ldsm4(q, baseBhi + tB + 8192);
            bh[2][0]=q[0]; bh[2][1]=q[1]; bh[3][0]=q[2]; bh[3][1]=q[3];
            ldsm4(q, baseBlo + tB);
            bl[0][0]=q[0]; bl[0][1]=q[1]; bl[1][0]=q[2]; bl[1][1]=q[3];
            ldsm4(q, baseBlo + tB + 8192);
            bl[2][0]=q[0]; bl[2][1]=q[1]; bl[3][0]=q[2]; bl[3][1]=q[3];
            #pragma unroll
            for (int ni = 0; ni < 4; ni++) {
                mma_bf16(acc[0][ni], ah0, bh[ni]);
                mma_bf16(acc[1][ni], ah1, bh[ni]);
                mma_bf16(acc[0][ni], al0, bh[ni]);
                mma_bf16(acc[1][ni], al1, bh[ni]);
                mma_bf16(acc[0][ni], ah0, bl[ni]);
                mma_bf16(acc[1][ni], ah1, bl[ni]);
            }
        }
        __syncthreads();          // buf1 + B reads done
        if (!last_it && tid == 0) {
            const char* hi = (const char*)g_Ahi + (size_t)(mid_idx - 1) * 65536;
            const char* lo = (const char*)g_Alo + (size_t)(mid_idx - 1) * 65536;
            MBARRIER_EXPECT_TX(mb1, 65536);
            BULK_CP(sbase + OFF_A1HI, hi + 32768, 32768, mb1);
            BULK_CP(sbase + OFF_A1LO, lo + 32768, 32768, mb1);
        }

        // ===== epilogue: C frags -> V[s][l] =====
        const int rr = lane >> 2, cq = (lane & 3) * 2;
        #pragma unroll
        for (int mi = 0; mi < 2; mi++)
            #pragma unroll
            for (int ni = 0; ni < 4; ni++) {
                const int l = m_base + 16 * mi + rr;
                const int s = s_base + 8 * ni + cq;
                V[s * VSTRIDE + l]           = acc[mi][ni][0];
                V[(s + 1) * VSTRIDE + l]     = acc[mi][ni][1];
                V[s * VSTRIDE + l + 8]       = acc[mi][ni][2];
                V[(s + 1) * VSTRIDE + l + 8] = acc[mi][ni][3];
            }
        __syncthreads();          // V complete

        if (!last_it) {
            const int s = tid & 63, p = tid >> 6;
            const float cp_ = g_phiC[(size_t)mid_idx * BATCH + b0 + s];
            const float sp_ = g_phiS[(size_t)mid_idx * BATCH + b0 + s];
            #pragma unroll 4
            for (int r = p * 32; r < p * 32 + 32; r += 4) {
                const float4 v = *(const float4*)&V[s * VSTRIDE + r];
                float4 f0 = make_float4(cp_*v.x, cp_*v.y, cp_*v.z, cp_*v.w);
                float4 f1 = make_float4(sp_*v.x, sp_*v.y, sp_*v.z, sp_*v.w);
                uint32_t h01,h23,l01,l23;
                const int ch0 = r >> 3;
                uint32_t o = (uint32_t)(s * 512 + (((ch0 & 24) | ((ch0 ^ (s & 7)) & 7)) << 4)
                                        + ((r & 7) << 1));
                split4(f0, h01,h23,l01,l23);
                *(uint2*)(sBh + o) = make_uint2(h01,h23);
                *(uint2*)(sBl + o) = make_uint2(l01,l23);
                const int ch1 = (DIM + r) >> 3;
                o = (uint32_t)(s * 512 + (((ch1 & 24) | ((ch1 ^ (s & 7)) & 7)) << 4)
                               + ((r & 7) << 1));
                split4(f1, h01,h23,l01,l23);
                *(uint2*)(sBh + o) = make_uint2(h01,h23);
                *(uint2*)(sBl + o) = make_uint2(l01,l23);
            }
        } else if (tid < TSS) {
            const int s = tid;
            const float c0 = g_phiC[b0 + s];
            const float s0 = g_phiS[b0 + s];
            float accs = 0.0f;
            #pragma unroll 4
            for (int l = 0; l < DIM; l++) {
                const float lv = fmaf(first[l], c0, first[DIM + l] * s0);
                accs = fmaf(lv, V[s * VSTRIDE + l], accs);
            }
            #pragma unroll
            for (int o = 0; o < NOUT; o++)
                out[(b0 + s) * NOUT + o] = fmaf(accs, wlin[o], blin[o]);
        }
        __syncthreads();
    }
}

// ---------------------------------------------------------------------------
extern "C" void kernel_launch(void* const* d_in, const int* in_sizes, int n_in,
                              void* d_out, int out_size) {
    const float* x     = (const float*)d_in[0];
    const float* first = (const float*)d_in[1];
    const float* mid   = (const float*)d_in[2];
    const float* last  = (const float*)d_in[3];
    const float* wlin  = (const float*)d_in[4];
    const float* blin  = (const float*)d_in[5];
    float* out = (float*)d_out;

    cudaFuncSetAttribute(mps_mma, cudaFuncAttributeMaxDynamicSharedMemorySize,
                         SMEM_TOTAL);

    split_mid<<<(MIDSITES * DIM * K2 / 4 + 255) / 256, 256>>>(mid);
    phi_kernel<<<BATCH, NSITES>>>(x);
    mps_mma<<<BATCH / TSS, NTHREADS, SMEM_TOTAL>>>(first, last, wlin, blin, out);
}

// round 8
// speedup vs baseline: 3.4340x; 1.2185x over previous
#include <cuda_runtime.h>
#include <cuda_bf16.h>
#include <cstdint>
#include <math.h>

#define BATCH    8192
#define NSITES   256
#define DIM      128
#define NOUT     10
#define TSS      64
#define NTHREADS 256
#define MIDSITES 254
#define VSTRIDE  132

// smem byte offsets
#define OFF_BUF0 0        // 64 KB : A k-half 0  [g][hi/lo][128 l][64 k] swizzled
#define OFF_BUF1 65536    // 64 KB : A k-half 1
#define OFF_BH   131072   // 16 KB : B_hi [128 k][64 s] bf16, swizzled 128B rows
#define OFF_BL   147456   // 16 KB : B_lo
#define OFF_V    163840   // 33792 B : V [64 s][132 l] fp32 (also phi staging)
#define OFF_MB0  197632
#define OFF_MB1  197640
#define SMEM_TOTAL 197648

__device__ float    g_phiC[NSITES * BATCH];
__device__ float    g_phiS[NSITES * BATCH];
// per site 131072 B: [khalf(2)][g(2)][part hi/lo(2)][l(128)][64 k bf16] swizzled
__device__ uint16_t g_A[(size_t)MIDSITES * 65536];

// ---------------------------------------------------------------------------
// helpers
// ---------------------------------------------------------------------------
__device__ __forceinline__ void split4(float4 f, uint32_t& h01, uint32_t& h23,
                                       uint32_t& l01, uint32_t& l23) {
    asm("cvt.rn.bf16x2.f32 %0, %1, %2;" : "=r"(h01) : "f"(f.y), "f"(f.x));
    asm("cvt.rn.bf16x2.f32 %0, %1, %2;" : "=r"(h23) : "f"(f.w), "f"(f.z));
    const float hx = __uint_as_float(h01 << 16);
    const float hy = __uint_as_float(h01 & 0xffff0000u);
    const float hz = __uint_as_float(h23 << 16);
    const float hw = __uint_as_float(h23 & 0xffff0000u);
    const float lx = f.x - hx, ly = f.y - hy, lz = f.z - hz, lw = f.w - hw;
    asm("cvt.rn.bf16x2.f32 %0, %1, %2;" : "=r"(l01) : "f"(ly), "f"(lx));
    asm("cvt.rn.bf16x2.f32 %0, %1, %2;" : "=r"(l23) : "f"(lw), "f"(lz));
}

__device__ __forceinline__ void split2(float v0, float v1, uint32_t& hh, uint32_t& ll) {
    asm("cvt.rn.bf16x2.f32 %0, %1, %2;" : "=r"(hh) : "f"(v1), "f"(v0));
    const float h0 = __uint_as_float(hh << 16);
    const float h1 = __uint_as_float(hh & 0xffff0000u);
    const float l0 = v0 - h0, l1 = v1 - h1;
    asm("cvt.rn.bf16x2.f32 %0, %1, %2;" : "=r"(ll) : "f"(l1), "f"(l0));
}

__device__ __forceinline__ void ldsm4(uint32_t r[4], uint32_t addr) {
    asm volatile("ldmatrix.sync.aligned.m8n8.x4.shared.b16 {%0,%1,%2,%3}, [%4];"
                 : "=r"(r[0]), "=r"(r[1]), "=r"(r[2]), "=r"(r[3]) : "r"(addr));
}
__device__ __forceinline__ void ldsm4t(uint32_t r[4], uint32_t addr) {
    asm volatile("ldmatrix.sync.aligned.m8n8.x4.trans.shared.b16 {%0,%1,%2,%3}, [%4];"
                 : "=r"(r[0]), "=r"(r[1]), "=r"(r[2]), "=r"(r[3]) : "r"(addr));
}

__device__ __forceinline__ void mma_bf16(float c[4], const uint32_t a[4],
                                         const uint32_t b[2]) {
    asm volatile("mma.sync.aligned.m16n8k16.row.col.f32.bf16.bf16.f32 "
                 "{%0,%1,%2,%3}, {%4,%5,%6,%7}, {%8,%9}, {%0,%1,%2,%3};"
                 : "+f"(c[0]), "+f"(c[1]), "+f"(c[2]), "+f"(c[3])
                 : "r"(a[0]), "r"(a[1]), "r"(a[2]), "r"(a[3]),
                   "r"(b[0]), "r"(b[1]));
}

__device__ __forceinline__ void mma_group(float acc[2][4][4],
        const uint32_t ah0[4], const uint32_t ah1[4],
        const uint32_t al0[4], const uint32_t al1[4],
        const uint32_t bh[4][2], const uint32_t bl[4][2]) {
    #pragma unroll
    for (int ni = 0; ni < 4; ni++) {
        mma_bf16(acc[0][ni], ah0, bh[ni]);
        mma_bf16(acc[1][ni], ah1, bh[ni]);
        mma_bf16(acc[0][ni], al0, bh[ni]);
        mma_bf16(acc[1][ni], al1, bh[ni]);
        mma_bf16(acc[0][ni], ah0, bl[ni]);
        mma_bf16(acc[1][ni], ah1, bl[ni]);
    }
}

#define MBARRIER_INIT(a, c) \
    asm volatile("mbarrier.init.shared.b64 [%0], %1;" \
                 :: "r"((uint32_t)(a)), "r"((uint32_t)(c)) : "memory")
#define MBARRIER_EXPECT_TX(a, n) \
    asm volatile("mbarrier.arrive.expect_tx.shared.b64 _, [%0], %1;" \
                 :: "r"((uint32_t)(a)), "r"((uint32_t)(n)) : "memory")
#define BULK_CP(dst, src, n, mbar) \
    asm volatile("cp.async.bulk.shared::cluster.global.mbarrier::complete_tx::bytes " \
                 "[%0], [%1], %2, [%3];" \
                 :: "r"((uint32_t)(dst)), "l"(src), "r"((uint32_t)(n)), \
                    "r"((uint32_t)(mbar)) : "memory")
#define MBAR_WAIT(mbar, ph) do {                                             \
    uint32_t _m = (uint32_t)(mbar); uint32_t _p = (uint32_t)(ph);            \
    asm volatile("{\n\t.reg .pred P1;\n\t"                                   \
        "WAIT_%=:\n\t"                                                        \
        "mbarrier.try_wait.parity.acquire.cta.shared::cta.b64 P1, [%0], %1, 0x989680;\n\t" \
        "@P1 bra.uni DONE_%=;\n\t"                                            \
        "bra.uni WAIT_%=;\n\t"                                                \
        "DONE_%=:\n\t}" :: "r"(_m), "r"(_p) : "memory");                      \
} while (0)

// ---------------------------------------------------------------------------
// Kernel 0: split mid into bf16 hi/lo, [khalf][g][part] swizzled layout
// ---------------------------------------------------------------------------
__global__ void split_mid(const float* __restrict__ mid) {
    const int gid = blockIdx.x * blockDim.x + threadIdx.x;
    if (gid >= MIDSITES * 8192) return;
    const int site = gid >> 13;
    const int q    = gid & 8191;
    const int l    = q >> 6;
    const int d    = (q >> 5) & 1;
    const int r    = (q & 31) << 2;
    const float4 w = *(const float4*)(mid + (size_t)site * 32768 + l * 256 + d * 128 + r);
    uint32_t h01, h23, l01, l23;
    split4(w, h01, h23, l01, l23);
    const int khalf = r >> 6, rcol = r & 63;
    const size_t base = (size_t)site * 131072 + (size_t)khalf * 65536
                      + (size_t)d * 32768 + (size_t)l * 128
                      + (uint32_t)((((rcol >> 3) ^ (l & 7)) & 7) << 4)
                      + (uint32_t)((r & 7) << 1);
    *(uint2*)((char*)g_A + base)         = make_uint2(h01, h23);
    *(uint2*)((char*)g_A + base + 16384) = make_uint2(l01, l23);
}

// ---------------------------------------------------------------------------
// Kernel 1: feature map
// ---------------------------------------------------------------------------
__global__ void phi_kernel(const float* __restrict__ x) {
    const int b = blockIdx.x;
    const int n = threadIdx.x;
    const float v = x[b * NSITES + n];
    float mn = v, mx = v;
    #pragma unroll
    for (int off = 16; off > 0; off >>= 1) {
        mn = fminf(mn, __shfl_xor_sync(0xffffffffu, mn, off));
        mx = fmaxf(mx, __shfl_xor_sync(0xffffffffu, mx, off));
    }
    __shared__ float smn[8], smx[8];
    const int w = n >> 5, lane = n & 31;
    if (lane == 0) { smn[w] = mn; smx[w] = mx; }
    __syncthreads();
    mn = smn[0]; mx = smx[0];
    #pragma unroll
    for (int i = 1; i < 8; i++) { mn = fminf(mn, smn[i]); mx = fmaxf(mx, smx[i]); }
    const float ang = 1.57079632679489662f * (v - mn) / (mx - mn + 1e-6f);
    g_phiC[n * BATCH + b] = cosf(ang);
    g_phiS[n * BATCH + b] = sinf(ang);
}

// ---------------------------------------------------------------------------
// Kernel 2: reversed-chain MPS; per site two GEMMs D0=M0·v, D1=M1·v (K=128),
// phi combine fused into the fragment epilogue which writes B directly.
// ---------------------------------------------------------------------------
extern __shared__ char smem_raw[];

__device__ __forceinline__ void do_khalf(
        uint32_t abuf, int kh,
        uint32_t bh0, uint32_t bh1, uint32_t bl0, uint32_t bl1,
        int cA, int r7a,
        float acc0[2][4][4], float acc1[2][4][4]) {
    #pragma unroll
    for (int st = 0; st < 4; st++) {
        const uint32_t kb = (uint32_t)((kh + st * 16) * 128);
        uint32_t q[4];
        uint32_t bh[4][2], bl[4][2];
        ldsm4t(q, bh0 + kb);
        bh[0][0]=q[0]; bh[0][1]=q[1]; bh[1][0]=q[2]; bh[1][1]=q[3];
        ldsm4t(q, bh1 + kb);
        bh[2][0]=q[0]; bh[2][1]=q[1]; bh[3][0]=q[2]; bh[3][1]=q[3];
        ldsm4t(q, bl0 + kb);
        bl[0][0]=q[0]; bl[0][1]=q[1]; bl[1][0]=q[2]; bl[1][1]=q[3];
        ldsm4t(q, bl1 + kb);
        bl[2][0]=q[0]; bl[2][1]=q[1]; bl[3][0]=q[2]; bl[3][1]=q[3];

        const uint32_t tA = (uint32_t)((((2 * st + cA) ^ r7a) & 7) << 4);
        uint32_t ah0[4], ah1[4], al0[4], al1[4];
        ldsm4(ah0, abuf + tA);
        ldsm4(ah1, abuf + tA + 2048);
        ldsm4(al0, abuf + tA + 16384);
        ldsm4(al1, abuf + tA + 18432);
        mma_group(acc0, ah0, ah1, al0, al1, bh, bl);
        ldsm4(ah0, abuf + tA + 32768);
        ldsm4(ah1, abuf + tA + 34816);
        ldsm4(al0, abuf + tA + 49152);
        ldsm4(al1, abuf + tA + 51200);
        mma_group(acc1, ah0, ah1, al0, al1, bh, bl);
    }
}

__global__ __launch_bounds__(NTHREADS, 1)
void mps_mma(const float* __restrict__ first,
             const float* __restrict__ last,
             const float* __restrict__ wlin,
             const float* __restrict__ blin,
             float* __restrict__ out) {
    const uint32_t sbase = (uint32_t)__cvta_generic_to_shared(smem_raw);
    float* V = (float*)(smem_raw + OFF_V);
    const uint32_t mb0 = sbase + OFF_MB0, mb1 = sbase + OFF_MB1;
    const int tid  = threadIdx.x;
    const int wid  = tid >> 5, lane = tid & 31;
    const int b0   = blockIdx.x * TSS;
    const int wm   = wid & 3, wn = wid >> 2;
    const int m_base = wm * 32, s_base = wn * 32;

    // A ldmatrix lane consts (128B rows)
    const int rowA = m_base + (lane & 15);
    const int cA   = lane >> 4;
    const int r7a  = rowA & 7;
    const uint32_t abuf0 = sbase + OFF_BUF0 + rowA * 128;
    const uint32_t abuf1 = sbase + OFF_BUF1 + rowA * 128;

    // B ldmatrix.trans lane consts ([k][s] layout, 128B rows)
    const int mB    = lane >> 3;
    const int kofsB = (mB & 1) * 8 + (lane & 7);
    const int sc0   = s_base + ((mB >> 1) << 3);
    const uint32_t bh0 = sbase + OFF_BH + kofsB * 128
                       + (uint32_t)(((((sc0)      >> 3) ^ (kofsB & 7)) & 7) << 4);
    const uint32_t bh1 = sbase + OFF_BH + kofsB * 128
                       + (uint32_t)(((((sc0 + 16) >> 3) ^ (kofsB & 7)) & 7) << 4);
    const uint32_t bl0 = bh0 + (OFF_BL - OFF_BH);
    const uint32_t bl1 = bh1 + (OFF_BL - OFF_BH);

    // epilogue lane consts
    const int rr = lane >> 2, cq = (lane & 3) * 2;
    const int snib = s_base >> 3;

    if (tid == 0) { MBARRIER_INIT(mb0, 1); MBARRIER_INIT(mb1, 1); }
    __syncthreads();

    // prologue TMA: site 253, both k-halves
    if (tid == 0) {
        const char* src = (const char*)g_A + (size_t)(MIDSITES - 1) * 131072;
        MBARRIER_EXPECT_TX(mb0, 65536);
        BULK_CP(sbase + OFF_BUF0, src, 65536, mb0);
        MBARRIER_EXPECT_TX(mb1, 65536);
        BULK_CP(sbase + OFF_BUF1, src + 65536, 65536, mb1);
    }

    // initial B = R_254[r] = last[r,0]*c255 + last[r,1]*s255 (unscaled)
    if (tid < 64)        V[tid]      = g_phiC[(size_t)(NSITES - 1) * BATCH + b0 + tid];
    else if (tid < 128)  V[tid]      = g_phiS[(size_t)(NSITES - 1) * BATCH + b0 + tid - 64];
    __syncthreads();
    {
        const int r = tid >> 1;
        const int sblk = (tid & 1) * 32;
        const float l0 = last[2 * r], l1 = last[2 * r + 1];
        for (int s = sblk; s < sblk + 32; s += 2) {
            const float v0 = l0 * V[s]     + l1 * V[64 + s];
            const float v1 = l0 * V[s + 1] + l1 * V[64 + s + 1];
            uint32_t hh, ll;
            split2(v0, v1, hh, ll);
            const uint32_t o = (uint32_t)(r * 128)
                             + (uint32_t)((((s >> 3) ^ (r & 7)) & 7) << 4)
                             + (uint32_t)((s & 7) << 1);
            *(uint32_t*)(smem_raw + OFF_BH + o) = hh;
            *(uint32_t*)(smem_raw + OFF_BL + o) = ll;
        }
    }
    __syncthreads();

    for (int it = 0; it < MIDSITES; ++it) {
        const int i = MIDSITES - 1 - it;          // mid index
        const bool last_it = (it == MIDSITES - 1);
        const int ph = it & 1;

        // prefetch phi[site i+1] for the epilogue combine
        float2 pc[4], ps[4];
        {
            const size_t pb = (size_t)(i + 1) * BATCH + b0 + s_base + cq;
            #pragma unroll
            for (int ni = 0; ni < 4; ni++) {
                pc[ni] = *(const float2*)&g_phiC[pb + 8 * ni];
                ps[ni] = *(const float2*)&g_phiS[pb + 8 * ni];
            }
        }

        float acc0[2][4][4], acc1[2][4][4];
        #pragma unroll
        for (int mi = 0; mi < 2; mi++)
            #pragma unroll
            for (int ni = 0; ni < 4; ni++)
                #pragma unroll
                for (int e = 0; e < 4; e++) { acc0[mi][ni][e] = 0.0f; acc1[mi][ni][e] = 0.0f; }

        // ===== k-half 0 =====
        MBAR_WAIT(mb0, ph);
        do_khalf(abuf0, 0, bh0, bh1, bl0, bl1, cA, r7a, acc0, acc1);
        __syncthreads();
        if (!last_it && tid == 0) {
            const char* src = (const char*)g_A + (size_t)(i - 1) * 131072;
            MBARRIER_EXPECT_TX(mb0, 65536);
            BULK_CP(sbase + OFF_BUF0, src, 65536, mb0);
        }

        // ===== k-half 1 =====
        MBAR_WAIT(mb1, ph);
        do_khalf(abuf1, 64, bh0, bh1, bl0, bl1, cA, r7a, acc0, acc1);
        __syncthreads();   // A buf1 + B reads done
        if (!last_it && tid == 0) {
            const char* src = (const char*)g_A + (size_t)(i - 1) * 131072;
            MBARRIER_EXPECT_TX(mb1, 65536);
            BULK_CP(sbase + OFF_BUF1, src + 65536, 65536, mb1);
        }

        // ===== fused epilogue: right = c*D0 + s*D1 -> next B (or V) =====
        if (!last_it) {
            #pragma unroll
            for (int ni = 0; ni < 4; ni++) {
                const float cx = pc[ni].x, cy = pc[ni].y;
                const float sx = ps[ni].x, sy = ps[ni].y;
                const uint32_t chs = (uint32_t)((((snib + ni) ^ rr) & 7) << 4)
                                   + (uint32_t)(cq << 1);
                #pragma unroll
                for (int mi = 0; mi < 2; mi++) {
                    const int r = m_base + 16 * mi + rr;
                    const float v0 = cx * acc0[mi][ni][0] + sx * acc1[mi][ni][0];
                    const float v1 = cy * acc0[mi][ni][1] + sy * acc1[mi][ni][1];
                    const float v2 = cx * acc0[mi][ni][2] + sx * acc1[mi][ni][2];
                    const float v3 = cy * acc0[mi][ni][3] + sy * acc1[mi][ni][3];
                    uint32_t hh, ll;
                    const uint32_t o = (uint32_t)(r * 128) + chs;
                    split2(v0, v1, hh, ll);
                    *(uint32_t*)(smem_raw + OFF_BH + o) = hh;
                    *(uint32_t*)(smem_raw + OFF_BL + o) = ll;
                    split2(v2, v3, hh, ll);
                    *(uint32_t*)(smem_raw + OFF_BH + o + 1024) = hh;
                    *(uint32_t*)(smem_raw + OFF_BL + o + 1024) = ll;
                }
            }
        } else {
            #pragma unroll
            for (int ni = 0; ni < 4; ni++) {
                const float cx = pc[ni].x, cy = pc[ni].y;
                const float sx = ps[ni].x, sy = ps[ni].y;
                const int s = s_base + 8 * ni + cq;
                #pragma unroll
                for (int mi = 0; mi < 2; mi++) {
                    const int r = m_base + 16 * mi + rr;
                    V[s * VSTRIDE + r]           = cx * acc0[mi][ni][0] + sx * acc1[mi][ni][0];
                    V[(s + 1) * VSTRIDE + r]     = cy * acc0[mi][ni][1] + sy * acc1[mi][ni][1];
                    V[s * VSTRIDE + r + 8]       = cx * acc0[mi][ni][2] + sx * acc1[mi][ni][2];
                    V[(s + 1) * VSTRIDE + r + 8] = cy * acc0[mi][ni][3] + sy * acc1[mi][ni][3];
                }
            }
        }
        __syncthreads();
    }

    // final head: scalar_s = sum_r (first[0][r]c0 + first[1][r]s0) * R_0[r]
    if (tid < TSS) {
        const int s = tid;
        const float c0 = g_phiC[b0 + s];
        const float s0 = g_phiS[b0 + s];
        float accs = 0.0f;
        #pragma unroll 4
        for (int l = 0; l < DIM; l++) {
            const float lv = fmaf(first[l], c0, first[DIM + l] * s0);
            accs = fmaf(lv, V[s * VSTRIDE + l], accs);
        }
        #pragma unroll
        for (int o = 0; o < NOUT; o++)
            out[(b0 + s) * NOUT + o] = fmaf(accs, wlin[o], blin[o]);
    }
}

// ---------------------------------------------------------------------------
extern "C" void kernel_launch(void* const* d_in, const int* in_sizes, int n_in,
                              void* d_out, int out_size) {
    const float* x     = (const float*)d_in[0];
    const float* first = (const float*)d_in[1];
    const float* mid   = (const float*)d_in[2];
    const float* last  = (const float*)d_in[3];
    const float* wlin  = (const float*)d_in[4];
    const float* blin  = (const float*)d_in[5];
    float* out = (float*)d_out;

    cudaFuncSetAttribute(mps_mma, cudaFuncAttributeMaxDynamicSharedMemorySize,
                         SMEM_TOTAL);

    split_mid<<<(MIDSITES * 8192 + 255) / 256, 256>>>(mid);
    phi_kernel<<<BATCH, NSITES>>>(x);
    mps_mma<<<BATCH / TSS, NTHREADS, SMEM_TOTAL>>>(first, last, wlin, blin, out);
}